// round 1
// baseline (speedup 1.0000x reference)
#include <cuda_runtime.h>
#include <math.h>

// ---------------------------------------------------------------- constants
#define NCELL 4096
#define NDRUG 2048
#define DIMF  2040
#define KNN_K 7
#define GAMMA_C 15.0f

static constexpr size_t S_NC = 4096, S_ND = 2048, S_D = 2040;

constexpr size_t OFF_AGGC = 0;                          // [NC,ND]
constexpr size_t OFF_AGGD = OFF_AGGC + S_NC * S_ND;     // [ND,NC]
constexpr size_t OFF_LAPC = OFF_AGGD + S_ND * S_NC;     // [NC,NC]
constexpr size_t OFF_LAPD = OFF_LAPC + S_NC * S_NC;     // [ND,ND]
constexpr size_t OFF_T1   = OFF_LAPD + S_ND * S_ND;     // [NC,D] temp
constexpr size_t OFF_SFC  = OFF_T1   + S_NC * S_D;      // [NC,D]
constexpr size_t OFF_SFD  = OFF_SFC  + S_NC * S_D;      // [ND,D]
constexpr size_t OFF_CP   = OFF_SFD  + S_ND * S_D;      // cellpre [NC,D]
constexpr size_t OFF_DP   = OFF_CP   + S_NC * S_D;      // drugpre [ND,D]
constexpr size_t OFF_XC   = OFF_DP   + S_ND * S_D;      // [NC,D]
constexpr size_t OFF_YC   = OFF_XC   + S_NC * S_D;      // [ND,D]
constexpr size_t OFF_RS   = OFF_YC   + S_ND * S_D;      // [NC]
constexpr size_t OFF_CS   = OFF_RS   + S_NC;            // [ND]
constexpr size_t OFF_DXA  = OFF_CS   + S_ND;            // [NC]
constexpr size_t OFF_DYA  = OFF_DXA  + S_NC;            // [ND]
constexpr size_t OFF_SELFC= OFF_DYA  + S_ND;            // [NC]
constexpr size_t OFF_SELFD= OFF_SELFC+ S_NC;            // [ND]
constexpr size_t OFF_THRC = OFF_SELFD+ S_ND;            // [NC]
constexpr size_t OFF_THRD = OFF_THRC + S_NC;            // [ND]
constexpr size_t OFF_DRC  = OFF_THRD + S_ND;            // [NC]
constexpr size_t OFF_DCC  = OFF_DRC  + S_NC;            // [NC]
constexpr size_t OFF_DRD  = OFF_DCC  + S_NC;            // [ND]
constexpr size_t OFF_DCD  = OFF_DRD  + S_ND;            // [ND]
constexpr size_t OFF_RNX  = OFF_DCD  + S_ND;            // [NC]
constexpr size_t OFF_RNY  = OFF_RNX  + S_NC;            // [ND]
constexpr size_t OFF_BSC  = OFF_RNY  + S_ND;            // [D]
constexpr size_t OFF_BSD  = OFF_BSC  + S_D;             // [D]
constexpr size_t SCRATCH_TOTAL = OFF_BSD + S_D;

__device__ float g_scratch[SCRATCH_TOTAL];

// ---------------------------------------------------------------- reductions
__device__ __forceinline__ float blockReduceSum(float v) {
    static __shared__ float sh[32];
    __syncthreads();   // safe for repeated calls in one kernel
    int lane = threadIdx.x & 31, w = threadIdx.x >> 5;
    #pragma unroll
    for (int o = 16; o; o >>= 1) v += __shfl_down_sync(0xffffffffu, v, o);
    if (lane == 0) sh[w] = v;
    __syncthreads();
    int nw = (blockDim.x + 31) >> 5;
    v = (threadIdx.x < nw) ? sh[threadIdx.x] : 0.f;
    if (w == 0) {
        #pragma unroll
        for (int o = 16; o; o >>= 1) v += __shfl_down_sync(0xffffffffu, v, o);
    }
    return v; // valid in thread 0
}

// ---------------------------------------------------------------- row / col sums
__global__ void rowsum_kernel(const float* __restrict__ A, int rows, int cols,
                              const float* __restrict__ thr, float* __restrict__ out) {
    int r = blockIdx.x;
    const float* p = A + (size_t)r * cols;
    float t = thr ? thr[r] : -1e30f;
    float s = 0.f;
    for (int j = threadIdx.x; j < cols; j += blockDim.x) {
        float v = p[j];
        s += (v >= t) ? v : 0.f;
    }
    s = blockReduceSum(s);
    if (threadIdx.x == 0) out[r] = s;
}

__global__ void colsum_kernel(const float* __restrict__ A, int rows, int cols,
                              const float* __restrict__ thr, float* __restrict__ out) {
    int c = blockIdx.x * blockDim.x + threadIdx.x;
    if (c >= cols) return;
    int r0 = blockIdx.y * 512;
    int r1 = min(r0 + 512, rows);
    float s = 0.f;
    for (int r = r0; r < r1; ++r) {
        float v = A[(size_t)r * cols + c];
        if (thr) v = (v >= thr[r]) ? v : 0.f;
        s += v;
    }
    atomicAdd(&out[c], s);
}

// ---------------------------------------------------------------- adj prep
__global__ void prep_adj_kernel(const float* __restrict__ rs, const float* __restrict__ cs,
                                float* __restrict__ dxa, float* __restrict__ dya,
                                float* __restrict__ selfc, float* __restrict__ selfd) {
    int i = blockIdx.x * blockDim.x + threadIdx.x;
    if (i < NCELL) {
        float r = rs[i] + 1.0f;
        dxa[i] = rsqrtf(r);
        selfc[i] = 1.0f / r + 1.0f;
    }
    if (i < NDRUG) {
        float c = cs[i] + 1.0f;
        dya[i] = rsqrtf(c);
        selfd[i] = 1.0f / c + 1.0f;
    }
}

__global__ void aggcell_kernel(const float* __restrict__ adj,
                               const float* __restrict__ dxa, const float* __restrict__ dya,
                               float* __restrict__ agg) {
    size_t idx = (size_t)blockIdx.x * blockDim.x + threadIdx.x;
    size_t total = (size_t)NCELL * NDRUG;
    if (idx >= total) return;
    int i = (int)(idx / NDRUG), j = (int)(idx % NDRUG);
    agg[idx] = adj[idx] * dxa[i] * dya[j];
}

__global__ void transpose_kernel(const float* __restrict__ A, int rows, int cols,
                                 float* __restrict__ B) {
    __shared__ float t[32][33];
    int x = blockIdx.x * 32 + threadIdx.x;
    int y = blockIdx.y * 32 + threadIdx.y;
    #pragma unroll
    for (int j = 0; j < 32; j += 8)
        if (x < cols && (y + j) < rows)
            t[threadIdx.y + j][threadIdx.x] = A[(size_t)(y + j) * cols + x];
    __syncthreads();
    x = blockIdx.y * 32 + threadIdx.x;   // col in B (= row in A)
    y = blockIdx.x * 32 + threadIdx.y;   // row in B (= col in A)
    #pragma unroll
    for (int j = 0; j < 32; j += 8)
        if (x < rows && (y + j) < cols)
            B[(size_t)(y + j) * rows + x] = t[threadIdx.x][threadIdx.y + j];
}

// ---------------------------------------------------------------- kNN threshold
__device__ __forceinline__ void topk_insert(float* v, float x) {
    if (x <= v[KNN_K - 1]) return;
    v[KNN_K - 1] = x;
    #pragma unroll
    for (int i = KNN_K - 1; i > 0; --i) {
        if (v[i] > v[i - 1]) { float t = v[i]; v[i] = v[i - 1]; v[i - 1] = t; }
    }
}

__global__ void knn_thr_kernel(const float* __restrict__ sim, int n, float* __restrict__ thr) {
    __shared__ float s[256 * KNN_K];
    int row = blockIdx.x, tid = threadIdx.x;
    float v[KNN_K];
    #pragma unroll
    for (int i = 0; i < KNN_K; i++) v[i] = -1e30f;
    const float* p = sim + (size_t)row * n;
    for (int j = tid; j < n; j += 256) topk_insert(v, p[j]);
    #pragma unroll
    for (int i = 0; i < KNN_K; i++) s[tid * KNN_K + i] = v[i];
    __syncthreads();
    for (int st = 128; st > 0; st >>= 1) {
        if (tid < st) {
            float* a = &s[tid * KNN_K];
            const float* b = &s[(tid + st) * KNN_K];
            #pragma unroll
            for (int i = 0; i < KNN_K; i++) v[i] = a[i];
            #pragma unroll
            for (int i = 0; i < KNN_K; i++) topk_insert(v, b[i]);
            #pragma unroll
            for (int i = 0; i < KNN_K; i++) a[i] = v[i];
        }
        __syncthreads();
    }
    if (tid == 0) thr[row] = s[KNN_K - 1];
}

__global__ void lap_kernel(const float* __restrict__ sim, int rows, int cols,
                           const float* __restrict__ thr,
                           const float* __restrict__ drow, const float* __restrict__ dcol,
                           float* __restrict__ lap) {
    size_t idx = (size_t)blockIdx.x * blockDim.x + threadIdx.x;
    size_t total = (size_t)rows * cols;
    if (idx >= total) return;
    int i = (int)(idx / cols), j = (int)(idx % cols);
    float v = sim[idx];
    lap[idx] = (v >= thr[i]) ? v * rsqrtf(drow[i]) * rsqrtf(dcol[j]) : 0.f;
}

// ---------------------------------------------------------------- bias sums
__global__ void bsum_kernel(const float* b0, const float* b1, const float* b2,
                            const float* c0, const float* c1, const float* c2,
                            float* bsc, float* bsd) {
    int j = blockIdx.x * blockDim.x + threadIdx.x;
    if (j < DIMF) {
        bsc[j] = b0[j] + b1[j] + b2[j];
        bsd[j] = c0[j] + c1[j] + c2[j];
    }
}

// ---------------------------------------------------------------- SGEMM
// C[M,N] = A[M,K] (optionally row-scaled) @ op(B); TRANSB ? B[N,K] : B[K,N]
#define F_ADD     1
#define F_RELU    2
#define F_PEARSON 4

template <bool TRANSB>
__global__ __launch_bounds__(256, 2)
void sgemm_kernel(int M, int N, int K,
                  const float* __restrict__ A, int lda, const float* __restrict__ rsA,
                  const float* __restrict__ B, int ldb,
                  float* __restrict__ C, int ldc,
                  const float* __restrict__ bias, int flags,
                  const float* __restrict__ rnx, const float* __restrict__ rny) {
    constexpr int BM = 128, BN = 128, BK = 8;
    __shared__ float As[BK][BM + 4];
    __shared__ float Bs[BK][BN + 4];
    int bm = blockIdx.y * BM, bn = blockIdx.x * BN;
    int tid = threadIdx.x;
    int tx = tid & 15, ty = tid >> 4;

    float acc[8][8];
    #pragma unroll
    for (int i = 0; i < 8; i++)
        #pragma unroll
        for (int j = 0; j < 8; j++) acc[i][j] = 0.f;

    for (int k0 = 0; k0 < K; k0 += BK) {
        // A tile: 128 x 8, each thread 4 consecutive-k elements
        {
            int lin = tid * 4;
            int m = lin >> 3, kk = lin & 7;
            int gm = bm + m;
            float vals[4];
            if (gm < M) {
                float rs = rsA ? rsA[gm] : 1.0f;
                #pragma unroll
                for (int u = 0; u < 4; u++) {
                    int gk = k0 + kk + u;
                    vals[u] = (gk < K) ? A[(size_t)gm * lda + gk] * rs : 0.f;
                }
            } else {
                #pragma unroll
                for (int u = 0; u < 4; u++) vals[u] = 0.f;
            }
            #pragma unroll
            for (int u = 0; u < 4; u++) As[kk + u][m] = vals[u];
        }
        // B tile
        if (TRANSB) {
            int lin = tid * 4;
            int n = lin >> 3, kk = lin & 7;
            int gn = bn + n;
            float vals[4];
            if (gn < N) {
                #pragma unroll
                for (int u = 0; u < 4; u++) {
                    int gk = k0 + kk + u;
                    vals[u] = (gk < K) ? B[(size_t)gn * ldb + gk] : 0.f;
                }
            } else {
                #pragma unroll
                for (int u = 0; u < 4; u++) vals[u] = 0.f;
            }
            #pragma unroll
            for (int u = 0; u < 4; u++) Bs[kk + u][n] = vals[u];
        } else {
            int kk = tid >> 5;
            int n = (tid & 31) * 4;
            int gk = k0 + kk;
            #pragma unroll
            for (int u = 0; u < 4; u++) {
                int gn = bn + n + u;
                Bs[kk][n + u] = (gk < K && gn < N) ? B[(size_t)gk * ldb + gn] : 0.f;
            }
        }
        __syncthreads();

        #pragma unroll
        for (int kk = 0; kk < BK; kk++) {
            float a[8], b[8];
            #pragma unroll
            for (int i = 0; i < 8; i++) a[i] = As[kk][ty * 8 + i];
            #pragma unroll
            for (int j = 0; j < 8; j++) b[j] = Bs[kk][tx * 8 + j];
            #pragma unroll
            for (int i = 0; i < 8; i++)
                #pragma unroll
                for (int j = 0; j < 8; j++) acc[i][j] = fmaf(a[i], b[j], acc[i][j]);
        }
        __syncthreads();
    }

    #pragma unroll
    for (int i = 0; i < 8; i++) {
        int gm = bm + ty * 8 + i;
        if (gm >= M) continue;
        #pragma unroll
        for (int j = 0; j < 8; j++) {
            int gn = bn + tx * 8 + j;
            if (gn >= N) continue;
            float v = acc[i][j];
            if (bias) v += bias[gn];
            size_t off = (size_t)gm * ldc + gn;
            if (flags & F_ADD)  v += C[off];
            if (flags & F_RELU) v = fmaxf(v, 0.f);
            if (flags & F_PEARSON) {
                float corr = v * rnx[gm] * rny[gn];
                v = 1.0f / (1.0f + expf(-GAMMA_C * corr));
            }
            C[off] = v;
        }
    }
}

// ---------------------------------------------------------------- gate + center
// g = relu(pre * (1 + gate)); xc = g - mean(g); rn = 1/||xc||
__global__ void gate_center_kernel(const float* __restrict__ pre, const float* __restrict__ gate,
                                   int cols, float* __restrict__ xc, float* __restrict__ rn) {
    extern __shared__ float row[];
    int r = blockIdx.x;
    size_t base = (size_t)r * cols;
    float s = 0.f;
    for (int j = threadIdx.x; j < cols; j += blockDim.x) {
        float g = pre[base + j] * (1.0f + gate[base + j]);
        g = fmaxf(g, 0.f);
        row[j] = g;
        s += g;
    }
    s = blockReduceSum(s);
    __shared__ float mean_s;
    if (threadIdx.x == 0) mean_s = s / (float)cols;
    __syncthreads();
    float mean = mean_s, q = 0.f;
    for (int j = threadIdx.x; j < cols; j += blockDim.x) {
        float c = row[j] - mean;
        xc[base + j] = c;
        q += c * c;
    }
    q = blockReduceSum(q);
    if (threadIdx.x == 0) rn[r] = rsqrtf(q);
}

// ---------------------------------------------------------------- host driver
static inline dim3 gemm_grid(int M, int N) {
    return dim3((N + 127) / 128, (M + 127) / 128);
}

extern "C" void kernel_launch(void* const* d_in, const int* in_sizes, int n_in,
                              void* d_out, int out_size) {
    const float* adj      = (const float*)d_in[0];
    const float* cell_sim = (const float*)d_in[1];
    const float* drug_sim = (const float*)d_in[2];
    const float* expm     = (const float*)d_in[3];
    const float* figm     = (const float*)d_in[4];
    const float* W_sc = (const float*)d_in[5];
    const float* W_sd = (const float*)d_in[6];
    const float* W_cs = (const float*)d_in[7];  const float* b_cs = (const float*)d_in[8];
    const float* W_c1 = (const float*)d_in[9];  const float* b_c1 = (const float*)d_in[10];
    const float* W_c2 = (const float*)d_in[11]; const float* b_c2 = (const float*)d_in[12];
    const float* W_ds = (const float*)d_in[13]; const float* b_ds = (const float*)d_in[14];
    const float* W_d1 = (const float*)d_in[15]; const float* b_d1 = (const float*)d_in[16];
    const float* W_d2 = (const float*)d_in[17]; const float* b_d2 = (const float*)d_in[18];
    float* out = (float*)d_out;

    float* S = nullptr;
    cudaGetSymbolAddress((void**)&S, g_scratch);

    float* AGGC = S + OFF_AGGC;  float* AGGD = S + OFF_AGGD;
    float* LAPC = S + OFF_LAPC;  float* LAPD = S + OFF_LAPD;
    float* T1   = S + OFF_T1;    float* SFC  = S + OFF_SFC;   float* SFD = S + OFF_SFD;
    float* CP   = S + OFF_CP;    float* DP   = S + OFF_DP;
    float* XC   = S + OFF_XC;    float* YC   = S + OFF_YC;
    float* RS   = S + OFF_RS;    float* CS   = S + OFF_CS;
    float* DXA  = S + OFF_DXA;   float* DYA  = S + OFF_DYA;
    float* SELFC= S + OFF_SELFC; float* SELFD= S + OFF_SELFD;
    float* THRC = S + OFF_THRC;  float* THRD = S + OFF_THRD;
    float* DRC  = S + OFF_DRC;   float* DCC  = S + OFF_DCC;
    float* DRD  = S + OFF_DRD;   float* DCD  = S + OFF_DCD;
    float* RNX  = S + OFF_RNX;   float* RNY  = S + OFF_RNY;
    float* BSC  = S + OFF_BSC;   float* BSD  = S + OFF_BSD;

    cudaStream_t st = 0;

    // ---- adjacency normalization ----
    rowsum_kernel<<<NCELL, 256, 0, st>>>(adj, NCELL, NDRUG, nullptr, RS);
    cudaMemsetAsync(CS, 0, S_ND * sizeof(float), st);
    colsum_kernel<<<dim3((NDRUG + 255) / 256, (NCELL + 511) / 512), 256, 0, st>>>(
        adj, NCELL, NDRUG, nullptr, CS);
    prep_adj_kernel<<<(NCELL + 255) / 256, 256, 0, st>>>(RS, CS, DXA, DYA, SELFC, SELFD);
    {
        size_t total = (size_t)NCELL * NDRUG;
        aggcell_kernel<<<(unsigned)((total + 255) / 256), 256, 0, st>>>(adj, DXA, DYA, AGGC);
    }
    transpose_kernel<<<dim3(NDRUG / 32, NCELL / 32), dim3(32, 8), 0, st>>>(AGGC, NCELL, NDRUG, AGGD);

    // ---- kNN laplacians ----
    knn_thr_kernel<<<NCELL, 256, 0, st>>>(cell_sim, NCELL, THRC);
    rowsum_kernel<<<NCELL, 256, 0, st>>>(cell_sim, NCELL, NCELL, THRC, DRC);
    cudaMemsetAsync(DCC, 0, S_NC * sizeof(float), st);
    colsum_kernel<<<dim3((NCELL + 255) / 256, (NCELL + 511) / 512), 256, 0, st>>>(
        cell_sim, NCELL, NCELL, THRC, DCC);
    {
        size_t total = (size_t)NCELL * NCELL;
        lap_kernel<<<(unsigned)((total + 255) / 256), 256, 0, st>>>(
            cell_sim, NCELL, NCELL, THRC, DRC, DCC, LAPC);
    }
    knn_thr_kernel<<<NDRUG, 256, 0, st>>>(drug_sim, NDRUG, THRD);
    rowsum_kernel<<<NDRUG, 256, 0, st>>>(drug_sim, NDRUG, NDRUG, THRD, DRD);
    cudaMemsetAsync(DCD, 0, S_ND * sizeof(float), st);
    colsum_kernel<<<dim3((NDRUG + 255) / 256, (NDRUG + 511) / 512), 256, 0, st>>>(
        drug_sim, NDRUG, NDRUG, THRD, DCD);
    {
        size_t total = (size_t)NDRUG * NDRUG;
        lap_kernel<<<(unsigned)((total + 255) / 256), 256, 0, st>>>(
            drug_sim, NDRUG, NDRUG, THRD, DRD, DCD, LAPD);
    }

    bsum_kernel<<<(DIMF + 255) / 256, 256, 0, st>>>(b_cs, b_c1, b_c2, b_ds, b_d1, b_d2, BSC, BSD);

    // ---- SimLayers ----
    // T1 = lap_c @ exp  (NN)
    sgemm_kernel<false><<<gemm_grid(NCELL, DIMF), 256, 0, st>>>(
        NCELL, DIMF, NCELL, LAPC, NCELL, nullptr, expm, DIMF, T1, DIMF, nullptr, 0, nullptr, nullptr);
    // SFC = relu(T1 @ W_sc^T) (NT)
    sgemm_kernel<true><<<gemm_grid(NCELL, DIMF), 256, 0, st>>>(
        NCELL, DIMF, DIMF, T1, DIMF, nullptr, W_sc, DIMF, SFC, DIMF, nullptr, F_RELU, nullptr, nullptr);
    // T1 = lap_d @ fig (NN)
    sgemm_kernel<false><<<gemm_grid(NDRUG, DIMF), 256, 0, st>>>(
        NDRUG, DIMF, NDRUG, LAPD, NDRUG, nullptr, figm, DIMF, T1, DIMF, nullptr, 0, nullptr, nullptr);
    // SFD = relu(T1 @ W_sd^T)
    sgemm_kernel<true><<<gemm_grid(NDRUG, DIMF), 256, 0, st>>>(
        NDRUG, DIMF, DIMF, T1, DIMF, nullptr, W_sd, DIMF, SFD, DIMF, nullptr, F_RELU, nullptr, nullptr);

    // ---- cell aggregation: CP = (selfc*exp)@Wcs^T + bsum + (aggc@fig)@Wc1^T + (aggc@sfd)@Wc2^T ----
    sgemm_kernel<true><<<gemm_grid(NCELL, DIMF), 256, 0, st>>>(
        NCELL, DIMF, DIMF, expm, DIMF, SELFC, W_cs, DIMF, CP, DIMF, BSC, 0, nullptr, nullptr);
    sgemm_kernel<false><<<gemm_grid(NCELL, DIMF), 256, 0, st>>>(
        NCELL, DIMF, NDRUG, AGGC, NDRUG, nullptr, figm, DIMF, T1, DIMF, nullptr, 0, nullptr, nullptr);
    sgemm_kernel<true><<<gemm_grid(NCELL, DIMF), 256, 0, st>>>(
        NCELL, DIMF, DIMF, T1, DIMF, nullptr, W_c1, DIMF, CP, DIMF, nullptr, F_ADD, nullptr, nullptr);
    sgemm_kernel<false><<<gemm_grid(NCELL, DIMF), 256, 0, st>>>(
        NCELL, DIMF, NDRUG, AGGC, NDRUG, nullptr, SFD, DIMF, T1, DIMF, nullptr, 0, nullptr, nullptr);
    sgemm_kernel<true><<<gemm_grid(NCELL, DIMF), 256, 0, st>>>(
        NCELL, DIMF, DIMF, T1, DIMF, nullptr, W_c2, DIMF, CP, DIMF, nullptr, F_ADD, nullptr, nullptr);
    gate_center_kernel<<<NCELL, 256, DIMF * sizeof(float), st>>>(CP, expm, DIMF, XC, RNX);

    // ---- drug aggregation ----
    sgemm_kernel<true><<<gemm_grid(NDRUG, DIMF), 256, 0, st>>>(
        NDRUG, DIMF, DIMF, figm, DIMF, SELFD, W_ds, DIMF, DP, DIMF, BSD, 0, nullptr, nullptr);
    sgemm_kernel<false><<<gemm_grid(NDRUG, DIMF), 256, 0, st>>>(
        NDRUG, DIMF, NCELL, AGGD, NCELL, nullptr, expm, DIMF, T1, DIMF, nullptr, 0, nullptr, nullptr);
    sgemm_kernel<true><<<gemm_grid(NDRUG, DIMF), 256, 0, st>>>(
        NDRUG, DIMF, DIMF, T1, DIMF, nullptr, W_d1, DIMF, DP, DIMF, nullptr, F_ADD, nullptr, nullptr);
    sgemm_kernel<false><<<gemm_grid(NDRUG, DIMF), 256, 0, st>>>(
        NDRUG, DIMF, NCELL, AGGD, NCELL, nullptr, SFC, DIMF, T1, DIMF, nullptr, 0, nullptr, nullptr);
    sgemm_kernel<true><<<gemm_grid(NDRUG, DIMF), 256, 0, st>>>(
        NDRUG, DIMF, DIMF, T1, DIMF, nullptr, W_d2, DIMF, DP, DIMF, nullptr, F_ADD, nullptr, nullptr);
    gate_center_kernel<<<NDRUG, 256, DIMF * sizeof(float), st>>>(DP, figm, DIMF, YC, RNY);

    // ---- decoder: out = sigmoid(GAMMA * (XC@YC^T) * rnx * rny) ----
    sgemm_kernel<true><<<gemm_grid(NCELL, NDRUG), 256, 0, st>>>(
        NCELL, NDRUG, DIMF, XC, DIMF, nullptr, YC, DIMF, out, NDRUG, nullptr, F_PEARSON, RNX, RNY);
}